// round 1
// baseline (speedup 1.0000x reference)
#include <cuda_runtime.h>
#include <math.h>

// Problem constants
#define D_MODEL 1024
#define N_HEADS 16
#define D_HEAD  64
#define SEQ     2048
#define BATCH   2
#define NTOK    (BATCH * SEQ)        // 4096
#define TRIPLE  (3 * D_MODEL)        // 3072

// Scratch (allocation-free rule: __device__ globals)
__device__ float g_qkv[(size_t)NTOK * TRIPLE];   // [token][3*D] : Q | K | V
__device__ float g_ctx[(size_t)NTOK * D_MODEL];  // [token][D]

// ----------------------------------------------------------------------------
// SGEMM: C[M,N] = A[M,K] @ B[K,N] + bias[N]
// BM=BN=128, BK=16, TM=TN=8, 256 threads. M,N,K divisible by tiles (checked by caller).
// ----------------------------------------------------------------------------
#define BM 128
#define BN 128
#define BKG 16
#define TM 8
#define TN 8

__global__ __launch_bounds__(256) void gemm_bias_kernel(
    const float* __restrict__ A, const float* __restrict__ B,
    const float* __restrict__ bias, float* __restrict__ C,
    int M, int N, int K)
{
    __shared__ float As[BKG][BM + 4];   // transposed A tile, padded
    __shared__ float Bs[BKG][BN];

    const int tid = threadIdx.x;
    const int tx  = tid & 15;           // 0..15 (N dir)
    const int ty  = tid >> 4;           // 0..15 (M dir)
    const long m0 = (long)blockIdx.y * BM;
    const long n0 = (long)blockIdx.x * BN;

    float acc[TM][TN];
    #pragma unroll
    for (int i = 0; i < TM; ++i)
        #pragma unroll
        for (int j = 0; j < TN; ++j) acc[i][j] = 0.f;

    for (int k0 = 0; k0 < K; k0 += BKG) {
        // Load A tile 128x16 (512 float4, 2 per thread), store transposed
        #pragma unroll
        for (int it = 0; it < 2; ++it) {
            int id = tid + it * 256;            // 0..511
            int r  = id >> 2;                   // 0..127
            int c4 = (id & 3) << 2;             // 0,4,8,12
            float4 v = *(const float4*)&A[(m0 + r) * (long)K + k0 + c4];
            As[c4 + 0][r] = v.x;
            As[c4 + 1][r] = v.y;
            As[c4 + 2][r] = v.z;
            As[c4 + 3][r] = v.w;
        }
        // Load B tile 16x128 (512 float4, 2 per thread)
        #pragma unroll
        for (int it = 0; it < 2; ++it) {
            int id = tid + it * 256;
            int r  = id >> 5;                   // 0..15
            int c4 = (id & 31) << 2;            // 0..124
            *(float4*)&Bs[r][c4] = *(const float4*)&B[(long)(k0 + r) * N + n0 + c4];
        }
        __syncthreads();

        #pragma unroll
        for (int kk = 0; kk < BKG; ++kk) {
            float ra[TM], rb[TN];
            #pragma unroll
            for (int i = 0; i < TM; ++i) ra[i] = As[kk][ty * TM + i];
            #pragma unroll
            for (int j = 0; j < TN; ++j) rb[j] = Bs[kk][tx * TN + j];
            #pragma unroll
            for (int i = 0; i < TM; ++i)
                #pragma unroll
                for (int j = 0; j < TN; ++j)
                    acc[i][j] += ra[i] * rb[j];
        }
        __syncthreads();
    }

    // Epilogue: bias add + float4 stores
    #pragma unroll
    for (int i = 0; i < TM; ++i) {
        long m = m0 + ty * TM + i;
        #pragma unroll
        for (int j = 0; j < TN; j += 4) {
            long n = n0 + tx * TN + j;
            float4 v;
            v.x = acc[i][j + 0] + bias[n + 0];
            v.y = acc[i][j + 1] + bias[n + 1];
            v.z = acc[i][j + 2] + bias[n + 2];
            v.w = acc[i][j + 3] + bias[n + 3];
            *(float4*)&C[m * (long)N + n] = v;
        }
    }
}

// ----------------------------------------------------------------------------
// Flash-attention style causal attention, fp32.
// Grid: (SEQ/64, N_HEADS, BATCH), 256 threads.
// Q tile 64 rows; loop K/V tiles of 64 up to the diagonal.
// Score tile 64x64 decomposed 4x4 per thread (16x16 thread grid).
// Dynamic smem: Qs[64][64] | Ks[64][65] | Vs[64][64] | Ps[64][65]
// ----------------------------------------------------------------------------
#define BQ 64
#define BKT 64
#define KS_STRIDE 65
#define PS_STRIDE 65

__global__ __launch_bounds__(256) void attn_kernel(
    const float* __restrict__ qkv, float* __restrict__ ctx)
{
    extern __shared__ float smem[];
    float* Qs = smem;                        // 64*64
    float* Ks = Qs + BQ * D_HEAD;            // 64*65
    float* Vs = Ks + BKT * KS_STRIDE;        // 64*64
    float* Ps = Vs + BKT * D_HEAD;           // 64*65

    const int tid = threadIdx.x;
    const int tx  = tid & 15;                // col / dim group
    const int ty  = tid >> 4;                // row group
    const int qt  = blockIdx.x;
    const int h   = blockIdx.y;
    const int b   = blockIdx.z;
    const int q0  = qt * BQ;

    const float scale = 0.125f;              // 1/sqrt(64)

    const size_t base_q = (size_t)b * SEQ * TRIPLE + (size_t)h * D_HEAD;
    const size_t base_k = base_q + D_MODEL;
    const size_t base_v = base_q + 2 * D_MODEL;

    // Load Q tile (64 rows x 64 dims), natural layout
    #pragma unroll
    for (int it = 0; it < 4; ++it) {
        int id = tid + it * 256;             // 0..1023 float4 ids
        int r  = id >> 4;                    // 0..63
        int d4 = (id & 15) << 2;             // 0..60
        float4 v = *(const float4*)&qkv[base_q + (size_t)(q0 + r) * TRIPLE + d4];
        *(float4*)&Qs[r * D_HEAD + d4] = v;
    }

    float m_run[4], l_run[4], acc[4][4];
    #pragma unroll
    for (int i = 0; i < 4; ++i) {
        m_run[i] = -1e30f;
        l_run[i] = 0.f;
        #pragma unroll
        for (int j = 0; j < 4; ++j) acc[i][j] = 0.f;
    }

    for (int kt = 0; kt <= qt; ++kt) {
        const int k0 = kt * BKT;
        __syncthreads();   // previous-iter consumers done; Q stores visible (iter 0)

        // Load K tile (64x64) into Ks (stride 65, scalar stores) and V tile into Vs
        #pragma unroll
        for (int it = 0; it < 4; ++it) {
            int id = tid + it * 256;
            int r  = id >> 4;
            int d4 = (id & 15) << 2;
            float4 kv = *(const float4*)&qkv[base_k + (size_t)(k0 + r) * TRIPLE + d4];
            Ks[r * KS_STRIDE + d4 + 0] = kv.x;
            Ks[r * KS_STRIDE + d4 + 1] = kv.y;
            Ks[r * KS_STRIDE + d4 + 2] = kv.z;
            Ks[r * KS_STRIDE + d4 + 3] = kv.w;
            float4 vv = *(const float4*)&qkv[base_v + (size_t)(k0 + r) * TRIPLE + d4];
            *(float4*)&Vs[r * D_HEAD + d4] = vv;
        }
        __syncthreads();

        // S = Q @ K^T  (4x4 microtile per thread)
        float s[4][4];
        #pragma unroll
        for (int i = 0; i < 4; ++i)
            #pragma unroll
            for (int j = 0; j < 4; ++j) s[i][j] = 0.f;

        #pragma unroll 16
        for (int kk = 0; kk < D_HEAD; ++kk) {
            float ra[4], rb[4];
            #pragma unroll
            for (int i = 0; i < 4; ++i) ra[i] = Qs[(ty * 4 + i) * D_HEAD + kk];
            #pragma unroll
            for (int j = 0; j < 4; ++j) rb[j] = Ks[(tx * 4 + j) * KS_STRIDE + kk];
            #pragma unroll
            for (int i = 0; i < 4; ++i)
                #pragma unroll
                for (int j = 0; j < 4; ++j)
                    s[i][j] += ra[i] * rb[j];
        }

        const bool diag = (kt == qt);

        // Online softmax update per row (mask BEFORE scale, per reference)
        #pragma unroll
        for (int i = 0; i < 4; ++i) {
            const int qrow = q0 + ty * 4 + i;
            float rmax = -1e30f;
            #pragma unroll
            for (int j = 0; j < 4; ++j) {
                float sv = s[i][j];
                if (diag) {
                    int kcol = k0 + tx * 4 + j;
                    if (kcol > qrow) sv = -1e9f;
                }
                sv *= scale;
                s[i][j] = sv;
                rmax = fmaxf(rmax, sv);
            }
            // reduce max over the 16 threads sharing this row (half-warp)
            #pragma unroll
            for (int off = 8; off >= 1; off >>= 1)
                rmax = fmaxf(rmax, __shfl_xor_sync(0xffffffffu, rmax, off));

            float mnew = fmaxf(m_run[i], rmax);
            float corr = __expf(m_run[i] - mnew);
            float psum = 0.f;
            #pragma unroll
            for (int j = 0; j < 4; ++j) {
                float p = __expf(s[i][j] - mnew);
                Ps[(tx * 4 + j) * PS_STRIDE + (ty * 4 + i)] = p;  // transposed
                psum += p;
            }
            #pragma unroll
            for (int off = 8; off >= 1; off >>= 1)
                psum += __shfl_xor_sync(0xffffffffu, psum, off);

            l_run[i] = l_run[i] * corr + psum;
            m_run[i] = mnew;
            #pragma unroll
            for (int j = 0; j < 4; ++j) acc[i][j] *= corr;
        }
        __syncthreads();

        // O += P @ V  (rows ty*4.., dims tx*4..)
        #pragma unroll 16
        for (int c = 0; c < BKT; ++c) {
            float rp[4];
            #pragma unroll
            for (int i = 0; i < 4; ++i) rp[i] = Ps[c * PS_STRIDE + ty * 4 + i];
            float4 rv4 = *(const float4*)&Vs[c * D_HEAD + tx * 4];
            float rv[4] = {rv4.x, rv4.y, rv4.z, rv4.w};
            #pragma unroll
            for (int i = 0; i < 4; ++i)
                #pragma unroll
                for (int j = 0; j < 4; ++j)
                    acc[i][j] += rp[i] * rv[j];
        }
    }

    // Epilogue: normalize and write ctx[token][h*64 + dim]
    #pragma unroll
    for (int i = 0; i < 4; ++i) {
        float invl = 1.0f / l_run[i];
        size_t row = (size_t)(b * SEQ + q0 + ty * 4 + i) * D_MODEL + (size_t)h * D_HEAD + tx * 4;
        float4 v;
        v.x = acc[i][0] * invl;
        v.y = acc[i][1] * invl;
        v.z = acc[i][2] * invl;
        v.w = acc[i][3] * invl;
        *(float4*)&ctx[row] = v;
    }
}

// ----------------------------------------------------------------------------
// Launch
// ----------------------------------------------------------------------------
extern "C" void kernel_launch(void* const* d_in, const int* in_sizes, int n_in,
                              void* d_out, int out_size)
{
    (void)in_sizes; (void)n_in; (void)out_size;
    const float* x      = (const float*)d_in[0];   // [2,2048,1024]
    const float* W_qkv  = (const float*)d_in[1];   // [1024,3072]
    const float* b_qkv  = (const float*)d_in[2];   // [3072]
    const float* W_proj = (const float*)d_in[3];   // [1024,1024]
    const float* b_proj = (const float*)d_in[4];   // [1024]
    float* out = (float*)d_out;                    // [2,2048,1024]

    float *qkv_buf = nullptr, *ctx_buf = nullptr;
    cudaGetSymbolAddress((void**)&qkv_buf, g_qkv);
    cudaGetSymbolAddress((void**)&ctx_buf, g_ctx);

    // 1) QKV projection: [4096,1024] @ [1024,3072] + b
    {
        dim3 grid(TRIPLE / BN, NTOK / BM);
        gemm_bias_kernel<<<grid, 256>>>(x, W_qkv, b_qkv, qkv_buf, NTOK, TRIPLE, D_MODEL);
    }

    // 2) Causal flash attention
    {
        const int smem_bytes = (BQ * D_HEAD + BKT * KS_STRIDE + BKT * D_HEAD + BKT * PS_STRIDE) * (int)sizeof(float);
        cudaFuncSetAttribute(attn_kernel, cudaFuncAttributeMaxDynamicSharedMemorySize, smem_bytes);
        dim3 grid(SEQ / BQ, N_HEADS, BATCH);
        attn_kernel<<<grid, 256, smem_bytes>>>(qkv_buf, ctx_buf);
    }

    // 3) Output projection: [4096,1024] @ [1024,1024] + b
    {
        dim3 grid(D_MODEL / BN, NTOK / BM);
        gemm_bias_kernel<<<grid, 256>>>(ctx_buf, W_proj, b_proj, out, NTOK, D_MODEL, D_MODEL);
    }
}

// round 3
// speedup vs baseline: 1.5715x; 1.5715x over previous
#include <cuda_runtime.h>
#include <cuda_bf16.h>
#include <math.h>
#include <stdint.h>

// Problem constants
#define D_MODEL 1024
#define N_HEADS 16
#define D_HEAD  64
#define SEQ     2048
#define BATCH   2
#define NTOK    (BATCH * SEQ)        // 4096
#define TRIPLE  (3 * D_MODEL)        // 3072
#define KP      3072                 // split-GEMM inner dim: 3 * 1024

// Scratch (allocation-free rule: __device__ globals)
__device__ float g_qkv[(size_t)NTOK * TRIPLE];            // fp32 Q|K|V
__device__ float g_ctx[(size_t)NTOK * D_MODEL];           // fp32 attention out
__device__ __nv_bfloat16 g_a [(size_t)NTOK * KP];         // A' = [ah|ah|al]
__device__ __nv_bfloat16 g_wq[(size_t)TRIPLE * KP];       // W_qkv'^T = [bh|bl|bh]
__device__ __nv_bfloat16 g_wp[(size_t)D_MODEL * KP];      // W_proj'^T

// ============================ helpers ========================================
__device__ __forceinline__ uint32_t smem_u32(const void* p) {
    uint32_t a;
    asm("{ .reg .u64 t; cvta.to.shared.u64 t, %1; cvt.u32.u64 %0, t; }" : "=r"(a) : "l"(p));
    return a;
}
#define SW128(off) ((off) ^ (((off) >> 3) & 0x70))

__device__ __forceinline__ void cp16(uint32_t dst, const void* src) {
    asm volatile("cp.async.cg.shared.global [%0], [%1], 16;" :: "r"(dst), "l"(src) : "memory");
}
#define CP_COMMIT() asm volatile("cp.async.commit_group;" ::: "memory")
#define CP_WAIT(n)  asm volatile("cp.async.wait_group %0;" :: "n"(n) : "memory")

__device__ __forceinline__ void ldmx4(uint32_t* r, uint32_t addr) {
    asm volatile("ldmatrix.sync.aligned.m8n8.x4.shared.b16 {%0,%1,%2,%3}, [%4];"
                 : "=r"(r[0]), "=r"(r[1]), "=r"(r[2]), "=r"(r[3]) : "r"(addr));
}
__device__ __forceinline__ void ldmx2(uint32_t* r, uint32_t addr) {
    asm volatile("ldmatrix.sync.aligned.m8n8.x2.shared.b16 {%0,%1}, [%2];"
                 : "=r"(r[0]), "=r"(r[1]) : "r"(addr));
}
__device__ __forceinline__ void mma16816(float* d, const uint32_t* a, const uint32_t* b) {
    asm volatile(
        "mma.sync.aligned.m16n8k16.row.col.f32.bf16.bf16.f32 "
        "{%0,%1,%2,%3}, {%4,%5,%6,%7}, {%8,%9}, {%0,%1,%2,%3};"
        : "+f"(d[0]), "+f"(d[1]), "+f"(d[2]), "+f"(d[3])
        : "r"(a[0]), "r"(a[1]), "r"(a[2]), "r"(a[3]), "r"(b[0]), "r"(b[1]));
}

// ============================ conversion kernels =============================
// A-side: src f32 [M][1024] -> dst bf16 [M][3072] as [hi | hi | lo]
__global__ __launch_bounds__(256) void convert_a_kernel(
    const float* __restrict__ src, __nv_bfloat16* __restrict__ dst, int total)
{
    int i = blockIdx.x * blockDim.x + threadIdx.x;
    if (i >= total) return;
    int m = i >> 10, k = i & 1023;
    float x = src[i];
    __nv_bfloat16 hi = __float2bfloat16(x);
    __nv_bfloat16 lo = __float2bfloat16(x - __bfloat162float(hi));
    size_t o = (size_t)m * KP + k;
    dst[o] = hi; dst[o + 1024] = hi; dst[o + 2048] = lo;
}

// W-side with transpose: W f32 [1024][N] -> dst bf16 [N][3072] as [hi | lo | hi]
__global__ __launch_bounds__(256) void convert_w_kernel(
    const float* __restrict__ W, __nv_bfloat16* __restrict__ dst, int N)
{
    __shared__ float tile[32][33];
    int n0 = blockIdx.x * 32, k0 = blockIdx.y * 32;
    int tx = threadIdx.x, ty = threadIdx.y;             // (32, 8)
    #pragma unroll
    for (int j = 0; j < 32; j += 8)
        tile[ty + j][tx] = W[(size_t)(k0 + ty + j) * N + n0 + tx];
    __syncthreads();
    #pragma unroll
    for (int j = 0; j < 32; j += 8) {
        int n = n0 + ty + j, k = k0 + tx;
        float x = tile[tx][ty + j];
        __nv_bfloat16 hi = __float2bfloat16(x);
        __nv_bfloat16 lo = __float2bfloat16(x - __bfloat162float(hi));
        size_t o = (size_t)n * KP + k;
        dst[o] = hi; dst[o + 1024] = lo; dst[o + 2048] = hi;
    }
}

// ============================ HMMA bf16 GEMM =================================
// C[M,N] = A'[M,KP] @ B'[N,KP]^T + bias[N]
// 128x128 CTA tile, 8 warps (2 M x 4 N), warp tile 64x32, mma.m16n8k16.
#define NSTAGES 3
#define NCHUNK  (KP / 64)            // 48 chunks of K=64 (128 bytes/row)
#define STAGE_BYTES 32768            // A 16KB + B 16KB
#define GEMM_SMEM (NSTAGES * STAGE_BYTES)

__global__ __launch_bounds__(256, 2) void gemm_hmma_kernel(
    const __nv_bfloat16* __restrict__ A, const __nv_bfloat16* __restrict__ B,
    const float* __restrict__ bias, float* __restrict__ C, int N)
{
    extern __shared__ char smem[];
    const uint32_t sb = smem_u32(smem);
    const int tid  = threadIdx.x;
    const int wid  = tid >> 5;
    const int lane = tid & 31;
    const int wm   = wid & 1;       // 0..1  (M dir, 64 rows each)
    const int wn   = wid >> 1;      // 0..3  (N dir, 32 cols each)
    const int m0   = blockIdx.y * 128;
    const int n0   = blockIdx.x * 128;

    float acc[4][4][4];
    #pragma unroll
    for (int i = 0; i < 4; ++i)
        #pragma unroll
        for (int j = 0; j < 4; ++j)
            #pragma unroll
            for (int r = 0; r < 4; ++r) acc[i][j][r] = 0.f;

    const __nv_bfloat16* Ab = A + (size_t)m0 * KP;
    const __nv_bfloat16* Bb = B + (size_t)n0 * KP;

    // chunk loader: A/B tiles 128 rows x 128B, SW128 swizzled, 8 cp.async/thread
    auto load_chunk = [&](int c) {
        int s = c % NSTAGES;
        uint32_t sa = sb + s * STAGE_BYTES;
        uint32_t sB = sa + 16384;
        size_t koff = (size_t)c * 64;
        #pragma unroll
        for (int t = 0; t < 4; ++t) {
            int id = tid + t * 256;
            int r = id >> 3, c16 = id & 7;
            uint32_t soff = SW128(r * 128 + c16 * 16);
            cp16(sa + soff, Ab + (size_t)r * KP + koff + c16 * 8);
            cp16(sB + soff, Bb + (size_t)r * KP + koff + c16 * 8);
        }
        CP_COMMIT();
    };

    // per-thread ldmatrix address components (within tile)
    const int a_row = wm * 64 + (lane & 15);          // + mt*16
    const int a_kb  = (lane >> 4) * 16;               // + kstep*32
    const int b_row = wn * 32 + (lane & 7);           // + nt*8
    const int b_kb  = ((lane >> 3) & 1) * 16;         // + kstep*32

    // prologue
    load_chunk(0);
    load_chunk(1);

    for (int c = 0; c < NCHUNK; ++c) {
        if (c == NCHUNK - 1) { CP_WAIT(0); } else { CP_WAIT(1); }
        __syncthreads();
        if (c + 2 < NCHUNK) load_chunk(c + 2);

        int s = c % NSTAGES;
        uint32_t sa = sb + s * STAGE_BYTES;
        uint32_t sB = sa + 16384;

        #pragma unroll
        for (int ks = 0; ks < 4; ++ks) {
            uint32_t afr[4][4], bfr[4][2];
            #pragma unroll
            for (int mt = 0; mt < 4; ++mt) {
                uint32_t off = (uint32_t)((a_row + mt * 16) * 128 + ks * 32 + a_kb);
                ldmx4(afr[mt], sa + SW128(off));
            }
            #pragma unroll
            for (int nt = 0; nt < 4; ++nt) {
                uint32_t off = (uint32_t)((b_row + nt * 8) * 128 + ks * 32 + b_kb);
                ldmx2(bfr[nt], sB + SW128(off));
            }
            #pragma unroll
            for (int mt = 0; mt < 4; ++mt)
                #pragma unroll
                for (int nt = 0; nt < 4; ++nt)
                    mma16816(acc[mt][nt], afr[mt], bfr[nt]);
        }
        // no trailing barrier needed: next iteration's CP_WAIT+__syncthreads
        // precedes any overwrite of this stage (3-stage rotation).
    }

    // epilogue: bias add + store (C fragment: c0/c1 row=lane/4, c2/c3 row+8)
    const int er = lane >> 2;
    const int ec = (lane & 3) * 2;
    #pragma unroll
    for (int mt = 0; mt < 4; ++mt) {
        #pragma unroll
        for (int nt = 0; nt < 4; ++nt) {
            int col = n0 + wn * 32 + nt * 8 + ec;
            float bx = bias[col], by = bias[col + 1];
            size_t r0 = (size_t)(m0 + wm * 64 + mt * 16 + er);
            float2 v0 = { acc[mt][nt][0] + bx, acc[mt][nt][1] + by };
            float2 v1 = { acc[mt][nt][2] + bx, acc[mt][nt][3] + by };
            *(float2*)&C[r0 * N + col]       = v0;
            *(float2*)&C[(r0 + 8) * N + col] = v1;
        }
    }
}

// ============================ attention (fp32 SIMT) ==========================
#define BQ 64
#define BKT 64
#define KS_STRIDE 65
#define PS_STRIDE 65

__global__ __launch_bounds__(256) void attn_kernel(
    const float* __restrict__ qkv, float* __restrict__ ctx)
{
    extern __shared__ float smemf[];
    float* Qs = smemf;
    float* Ks = Qs + BQ * D_HEAD;
    float* Vs = Ks + BKT * KS_STRIDE;
    float* Ps = Vs + BKT * D_HEAD;

    const int tid = threadIdx.x;
    const int tx  = tid & 15;
    const int ty  = tid >> 4;
    const int qt  = blockIdx.x;
    const int h   = blockIdx.y;
    const int b   = blockIdx.z;
    const int q0  = qt * BQ;
    const float scale = 0.125f;

    const size_t base_q = (size_t)b * SEQ * TRIPLE + (size_t)h * D_HEAD;
    const size_t base_k = base_q + D_MODEL;
    const size_t base_v = base_q + 2 * D_MODEL;

    #pragma unroll
    for (int it = 0; it < 4; ++it) {
        int id = tid + it * 256;
        int r  = id >> 4;
        int d4 = (id & 15) << 2;
        float4 v = *(const float4*)&qkv[base_q + (size_t)(q0 + r) * TRIPLE + d4];
        *(float4*)&Qs[r * D_HEAD + d4] = v;
    }

    float m_run[4], l_run[4], acc[4][4];
    #pragma unroll
    for (int i = 0; i < 4; ++i) {
        m_run[i] = -1e30f; l_run[i] = 0.f;
        #pragma unroll
        for (int j = 0; j < 4; ++j) acc[i][j] = 0.f;
    }

    for (int kt = 0; kt <= qt; ++kt) {
        const int k0 = kt * BKT;
        __syncthreads();
        #pragma unroll
        for (int it = 0; it < 4; ++it) {
            int id = tid + it * 256;
            int r  = id >> 4;
            int d4 = (id & 15) << 2;
            float4 kv = *(const float4*)&qkv[base_k + (size_t)(k0 + r) * TRIPLE + d4];
            Ks[r * KS_STRIDE + d4 + 0] = kv.x;
            Ks[r * KS_STRIDE + d4 + 1] = kv.y;
            Ks[r * KS_STRIDE + d4 + 2] = kv.z;
            Ks[r * KS_STRIDE + d4 + 3] = kv.w;
            float4 vv = *(const float4*)&qkv[base_v + (size_t)(k0 + r) * TRIPLE + d4];
            *(float4*)&Vs[r * D_HEAD + d4] = vv;
        }
        __syncthreads();

        float s[4][4];
        #pragma unroll
        for (int i = 0; i < 4; ++i)
            #pragma unroll
            for (int j = 0; j < 4; ++j) s[i][j] = 0.f;

        #pragma unroll 16
        for (int kk = 0; kk < D_HEAD; ++kk) {
            float ra[4], rb[4];
            #pragma unroll
            for (int i = 0; i < 4; ++i) ra[i] = Qs[(ty * 4 + i) * D_HEAD + kk];
            #pragma unroll
            for (int j = 0; j < 4; ++j) rb[j] = Ks[(tx * 4 + j) * KS_STRIDE + kk];
            #pragma unroll
            for (int i = 0; i < 4; ++i)
                #pragma unroll
                for (int j = 0; j < 4; ++j)
                    s[i][j] += ra[i] * rb[j];
        }

        const bool diag = (kt == qt);

        #pragma unroll
        for (int i = 0; i < 4; ++i) {
            const int qrow = q0 + ty * 4 + i;
            float rmax = -1e30f;
            #pragma unroll
            for (int j = 0; j < 4; ++j) {
                float sv = s[i][j];
                if (diag) {
                    int kcol = k0 + tx * 4 + j;
                    if (kcol > qrow) sv = -1e9f;
                }
                sv *= scale;
                s[i][j] = sv;
                rmax = fmaxf(rmax, sv);
            }
            #pragma unroll
            for (int off = 8; off >= 1; off >>= 1)
                rmax = fmaxf(rmax, __shfl_xor_sync(0xffffffffu, rmax, off));

            float mnew = fmaxf(m_run[i], rmax);
            float corr = __expf(m_run[i] - mnew);
            float psum = 0.f;
            #pragma unroll
            for (int j = 0; j < 4; ++j) {
                float p = __expf(s[i][j] - mnew);
                Ps[(tx * 4 + j) * PS_STRIDE + (ty * 4 + i)] = p;
                psum += p;
            }
            #pragma unroll
            for (int off = 8; off >= 1; off >>= 1)
                psum += __shfl_xor_sync(0xffffffffu, psum, off);

            l_run[i] = l_run[i] * corr + psum;
            m_run[i] = mnew;
            #pragma unroll
            for (int j = 0; j < 4; ++j) acc[i][j] *= corr;
        }
        __syncthreads();

        #pragma unroll 16
        for (int c = 0; c < BKT; ++c) {
            float rp[4];
            #pragma unroll
            for (int i = 0; i < 4; ++i) rp[i] = Ps[c * PS_STRIDE + ty * 4 + i];
            float4 rv4 = *(const float4*)&Vs[c * D_HEAD + tx * 4];
            float rv[4] = {rv4.x, rv4.y, rv4.z, rv4.w};
            #pragma unroll
            for (int i = 0; i < 4; ++i)
                #pragma unroll
                for (int j = 0; j < 4; ++j)
                    acc[i][j] += rp[i] * rv[j];
        }
    }

    #pragma unroll
    for (int i = 0; i < 4; ++i) {
        float invl = 1.0f / l_run[i];
        size_t row = (size_t)(b * SEQ + q0 + ty * 4 + i) * D_MODEL + (size_t)h * D_HEAD + tx * 4;
        float4 v;
        v.x = acc[i][0] * invl;
        v.y = acc[i][1] * invl;
        v.z = acc[i][2] * invl;
        v.w = acc[i][3] * invl;
        *(float4*)&ctx[row] = v;
    }
}

// ============================ launch =========================================
extern "C" void kernel_launch(void* const* d_in, const int* in_sizes, int n_in,
                              void* d_out, int out_size)
{
    (void)in_sizes; (void)n_in; (void)out_size;
    const float* x      = (const float*)d_in[0];
    const float* W_qkv  = (const float*)d_in[1];
    const float* b_qkv  = (const float*)d_in[2];
    const float* W_proj = (const float*)d_in[3];
    const float* b_proj = (const float*)d_in[4];
    float* out = (float*)d_out;

    float *qkv_buf = nullptr, *ctx_buf = nullptr;
    __nv_bfloat16 *a_buf = nullptr, *wq_buf = nullptr, *wp_buf = nullptr;
    cudaGetSymbolAddress((void**)&qkv_buf, g_qkv);
    cudaGetSymbolAddress((void**)&ctx_buf, g_ctx);
    cudaGetSymbolAddress((void**)&a_buf, g_a);
    cudaGetSymbolAddress((void**)&wq_buf, g_wq);
    cudaGetSymbolAddress((void**)&wp_buf, g_wp);

    static bool attr_set = false;
    if (!attr_set) {
        cudaFuncSetAttribute(gemm_hmma_kernel, cudaFuncAttributeMaxDynamicSharedMemorySize, GEMM_SMEM);
        const int attn_smem = (BQ * D_HEAD + BKT * KS_STRIDE + BKT * D_HEAD + BKT * PS_STRIDE) * (int)sizeof(float);
        cudaFuncSetAttribute(attn_kernel, cudaFuncAttributeMaxDynamicSharedMemorySize, attn_smem);
        attr_set = true;
    }
    const int attn_smem = (BQ * D_HEAD + BKT * KS_STRIDE + BKT * D_HEAD + BKT * PS_STRIDE) * (int)sizeof(float);

    // 1) convert x and W_qkv to bf16 splits
    convert_a_kernel<<<(NTOK * D_MODEL + 255) / 256, 256>>>(x, a_buf, NTOK * D_MODEL);
    {
        dim3 grid(TRIPLE / 32, D_MODEL / 32);
        convert_w_kernel<<<grid, dim3(32, 8)>>>(W_qkv, wq_buf, TRIPLE);
    }

    // 2) QKV GEMM: [4096,3072] = A'[4096,3072] @ Wq'[3072,3072]^T
    {
        dim3 grid(TRIPLE / 128, NTOK / 128);
        gemm_hmma_kernel<<<grid, 256, GEMM_SMEM>>>(a_buf, wq_buf, b_qkv, qkv_buf, TRIPLE);
    }

    // 3) causal flash attention (fp32 SIMT)
    {
        dim3 grid(SEQ / BQ, N_HEADS, BATCH);
        attn_kernel<<<grid, 256, attn_smem>>>(qkv_buf, ctx_buf);
    }

    // 4) convert ctx and W_proj
    convert_a_kernel<<<(NTOK * D_MODEL + 255) / 256, 256>>>(ctx_buf, a_buf, NTOK * D_MODEL);
    {
        dim3 grid(D_MODEL / 32, D_MODEL / 32);
        convert_w_kernel<<<grid, dim3(32, 8)>>>(W_proj, wp_buf, D_MODEL);
    }

    // 5) output projection
    {
        dim3 grid(D_MODEL / 128, NTOK / 128);
        gemm_hmma_kernel<<<grid, 256, GEMM_SMEM>>>(a_buf, wp_buf, b_proj, out, D_MODEL);
    }
}

// round 4
// speedup vs baseline: 2.8176x; 1.7930x over previous
#include <cuda_runtime.h>
#include <cuda_bf16.h>
#include <math.h>
#include <stdint.h>

// Problem constants
#define D_MODEL 1024
#define N_HEADS 16
#define D_HEAD  64
#define SEQ     2048
#define BATCH   2
#define NTOK    (BATCH * SEQ)        // 4096
#define TRIPLE  (3 * D_MODEL)        // 3072
#define KP      3072                 // split-GEMM inner dim: 3 * 1024

// Scratch (allocation-free rule: __device__ globals)
__device__ __nv_bfloat16 g_a [(size_t)NTOK * KP];         // A' = [ah|ah|al] (x, then ctx)
__device__ __nv_bfloat16 g_wq[(size_t)TRIPLE * KP];       // W_qkv'^T = [bh|bl|bh]
__device__ __nv_bfloat16 g_wp[(size_t)D_MODEL * KP];      // W_proj'^T
__device__ __nv_bfloat16 g_qh[(size_t)NTOK * TRIPLE];     // qkv hi (bf16)
__device__ __nv_bfloat16 g_ql[(size_t)NTOK * TRIPLE];     // qkv lo (bf16)

// ============================ helpers ========================================
__device__ __forceinline__ uint32_t smem_u32(const void* p) {
    uint32_t a;
    asm("{ .reg .u64 t; cvta.to.shared.u64 t, %1; cvt.u32.u64 %0, t; }" : "=r"(a) : "l"(p));
    return a;
}
#define SW128(off) ((off) ^ (((off) >> 3) & 0x70))

__device__ __forceinline__ void cp16(uint32_t dst, const void* src) {
    asm volatile("cp.async.cg.shared.global [%0], [%1], 16;" :: "r"(dst), "l"(src) : "memory");
}
#define CP_COMMIT() asm volatile("cp.async.commit_group;" ::: "memory")
#define CP_WAIT(n)  asm volatile("cp.async.wait_group %0;" :: "n"(n) : "memory")

__device__ __forceinline__ void ldmx4(uint32_t* r, uint32_t addr) {
    asm volatile("ldmatrix.sync.aligned.m8n8.x4.shared.b16 {%0,%1,%2,%3}, [%4];"
                 : "=r"(r[0]), "=r"(r[1]), "=r"(r[2]), "=r"(r[3]) : "r"(addr));
}
__device__ __forceinline__ void ldmx2(uint32_t* r, uint32_t addr) {
    asm volatile("ldmatrix.sync.aligned.m8n8.x2.shared.b16 {%0,%1}, [%2];"
                 : "=r"(r[0]), "=r"(r[1]) : "r"(addr));
}
__device__ __forceinline__ void ldmx2t(uint32_t* r, uint32_t addr) {
    asm volatile("ldmatrix.sync.aligned.m8n8.x2.trans.shared.b16 {%0,%1}, [%2];"
                 : "=r"(r[0]), "=r"(r[1]) : "r"(addr));
}
__device__ __forceinline__ void mma16816(float* d, const uint32_t* a, const uint32_t* b) {
    asm volatile(
        "mma.sync.aligned.m16n8k16.row.col.f32.bf16.bf16.f32 "
        "{%0,%1,%2,%3}, {%4,%5,%6,%7}, {%8,%9}, {%0,%1,%2,%3};"
        : "+f"(d[0]), "+f"(d[1]), "+f"(d[2]), "+f"(d[3])
        : "r"(a[0]), "r"(a[1]), "r"(a[2]), "r"(a[3]), "r"(b[0]), "r"(b[1]));
}
__device__ __forceinline__ uint32_t packbf2(float a, float b) {
    __nv_bfloat162 t = __floats2bfloat162_rn(a, b);   // x=a (low), y=b (high)
    return *reinterpret_cast<uint32_t*>(&t);
}
__device__ __forceinline__ void store_hilo2(__nv_bfloat16* hi_p, __nv_bfloat16* lo_p,
                                            float a, float b) {
    __nv_bfloat16 ha = __float2bfloat16(a), hb = __float2bfloat16(b);
    __nv_bfloat162 hv; hv.x = ha; hv.y = hb;
    __nv_bfloat162 lv;
    lv.x = __float2bfloat16(a - __bfloat162float(ha));
    lv.y = __float2bfloat16(b - __bfloat162float(hb));
    *reinterpret_cast<__nv_bfloat162*>(hi_p) = hv;
    *reinterpret_cast<__nv_bfloat162*>(lo_p) = lv;
}

// ============================ conversion kernels =============================
// A-side: src f32 [M][1024] -> dst bf16 [M][3072] as [hi | hi | lo]
__global__ __launch_bounds__(256) void convert_a_kernel(
    const float* __restrict__ src, __nv_bfloat16* __restrict__ dst, int total)
{
    int i = blockIdx.x * blockDim.x + threadIdx.x;
    if (i >= total) return;
    int m = i >> 10, k = i & 1023;
    float x = src[i];
    __nv_bfloat16 hi = __float2bfloat16(x);
    __nv_bfloat16 lo = __float2bfloat16(x - __bfloat162float(hi));
    size_t o = (size_t)m * KP + k;
    dst[o] = hi; dst[o + 1024] = hi; dst[o + 2048] = lo;
}

// W-side with transpose: W f32 [1024][N] -> dst bf16 [N][3072] as [hi | lo | hi]
__global__ __launch_bounds__(256) void convert_w_kernel(
    const float* __restrict__ W, __nv_bfloat16* __restrict__ dst, int N)
{
    __shared__ float tile[32][33];
    int n0 = blockIdx.x * 32, k0 = blockIdx.y * 32;
    int tx = threadIdx.x, ty = threadIdx.y;             // (32, 8)
    #pragma unroll
    for (int j = 0; j < 32; j += 8)
        tile[ty + j][tx] = W[(size_t)(k0 + ty + j) * N + n0 + tx];
    __syncthreads();
    #pragma unroll
    for (int j = 0; j < 32; j += 8) {
        int n = n0 + ty + j, k = k0 + tx;
        float x = tile[tx][ty + j];
        __nv_bfloat16 hi = __float2bfloat16(x);
        __nv_bfloat16 lo = __float2bfloat16(x - __bfloat162float(hi));
        size_t o = (size_t)n * KP + k;
        dst[o] = hi; dst[o + 1024] = lo; dst[o + 2048] = hi;
    }
}

// ============================ HMMA bf16 GEMM =================================
// C[M,N] = A'[M,KP] @ B'[N,KP]^T + bias[N]
// MODE 0: fp32 C out. MODE 1: bf16 hi/lo out (Chi/Clo).
#define NSTAGES 3
#define NCHUNK  (KP / 64)            // 48 chunks of K=64 (128 bytes/row)
#define STAGE_BYTES 32768            // A 16KB + B 16KB
#define GEMM_SMEM (NSTAGES * STAGE_BYTES)

template<int MODE>
__global__ __launch_bounds__(256, 2) void gemm_hmma_kernel(
    const __nv_bfloat16* __restrict__ A, const __nv_bfloat16* __restrict__ B,
    const float* __restrict__ bias, float* __restrict__ C,
    __nv_bfloat16* __restrict__ Chi, __nv_bfloat16* __restrict__ Clo, int N)
{
    extern __shared__ char smem[];
    const uint32_t sb = smem_u32(smem);
    const int tid  = threadIdx.x;
    const int wid  = tid >> 5;
    const int lane = tid & 31;
    const int wm   = wid & 1;
    const int wn   = wid >> 1;
    const int m0   = blockIdx.y * 128;
    const int n0   = blockIdx.x * 128;

    float acc[4][4][4];
    #pragma unroll
    for (int i = 0; i < 4; ++i)
        #pragma unroll
        for (int j = 0; j < 4; ++j)
            #pragma unroll
            for (int r = 0; r < 4; ++r) acc[i][j][r] = 0.f;

    const __nv_bfloat16* Ab = A + (size_t)m0 * KP;
    const __nv_bfloat16* Bb = B + (size_t)n0 * KP;

    auto load_chunk = [&](int c) {
        int s = c % NSTAGES;
        uint32_t sa = sb + s * STAGE_BYTES;
        uint32_t sB = sa + 16384;
        size_t koff = (size_t)c * 64;
        #pragma unroll
        for (int t = 0; t < 4; ++t) {
            int id = tid + t * 256;
            int r = id >> 3, c16 = id & 7;
            uint32_t soff = SW128(r * 128 + c16 * 16);
            cp16(sa + soff, Ab + (size_t)r * KP + koff + c16 * 8);
            cp16(sB + soff, Bb + (size_t)r * KP + koff + c16 * 8);
        }
        CP_COMMIT();
    };

    const int a_row = wm * 64 + (lane & 15);
    const int a_kb  = (lane >> 4) * 16;
    const int b_row = wn * 32 + (lane & 7);
    const int b_kb  = ((lane >> 3) & 1) * 16;

    load_chunk(0);
    load_chunk(1);

    for (int c = 0; c < NCHUNK; ++c) {
        if (c == NCHUNK - 1) { CP_WAIT(0); } else { CP_WAIT(1); }
        __syncthreads();
        if (c + 2 < NCHUNK) load_chunk(c + 2);

        int s = c % NSTAGES;
        uint32_t sa = sb + s * STAGE_BYTES;
        uint32_t sB = sa + 16384;

        #pragma unroll
        for (int ks = 0; ks < 4; ++ks) {
            uint32_t afr[4][4], bfr[4][2];
            #pragma unroll
            for (int mt = 0; mt < 4; ++mt) {
                uint32_t off = (uint32_t)((a_row + mt * 16) * 128 + ks * 32 + a_kb);
                ldmx4(afr[mt], sa + SW128(off));
            }
            #pragma unroll
            for (int nt = 0; nt < 4; ++nt) {
                uint32_t off = (uint32_t)((b_row + nt * 8) * 128 + ks * 32 + b_kb);
                ldmx2(bfr[nt], sB + SW128(off));
            }
            #pragma unroll
            for (int mt = 0; mt < 4; ++mt)
                #pragma unroll
                for (int nt = 0; nt < 4; ++nt)
                    mma16816(acc[mt][nt], afr[mt], bfr[nt]);
        }
    }

    const int er = lane >> 2;
    const int ec = (lane & 3) * 2;
    #pragma unroll
    for (int mt = 0; mt < 4; ++mt) {
        #pragma unroll
        for (int nt = 0; nt < 4; ++nt) {
            int col = n0 + wn * 32 + nt * 8 + ec;
            float bx = bias[col], by = bias[col + 1];
            size_t r0 = (size_t)(m0 + wm * 64 + mt * 16 + er);
            float v00 = acc[mt][nt][0] + bx, v01 = acc[mt][nt][1] + by;
            float v10 = acc[mt][nt][2] + bx, v11 = acc[mt][nt][3] + by;
            if (MODE == 0) {
                float2 a0 = { v00, v01 }, a1 = { v10, v11 };
                *(float2*)&C[r0 * N + col]       = a0;
                *(float2*)&C[(r0 + 8) * N + col] = a1;
            } else {
                store_hilo2(&Chi[r0 * N + col], &Clo[r0 * N + col], v00, v01);
                store_hilo2(&Chi[(r0 + 8) * N + col], &Clo[(r0 + 8) * N + col], v10, v11);
            }
        }
    }
}

// ============================ HMMA flash attention ===========================
// CTA: 128 Q rows x (head, batch). 8 warps, warp w owns rows w*16..+15.
// K/V tiles of 64, double-buffered. Split-precision on both MMAs.
// Output written directly in A' ([hi|hi|lo]) layout for the proj GEMM.
#define ABQ 128
#define ABK 64
#define ATTN_SMEM (32768 + 2 * 32768)   // Qh+Ql | 2 stages x (Kh,Kl,Vh,Vl)

__global__ __launch_bounds__(256, 1) void attn_hmma_kernel(
    const __nv_bfloat16* __restrict__ qkh, const __nv_bfloat16* __restrict__ qkl,
    __nv_bfloat16* __restrict__ ctxA)
{
    extern __shared__ char smem[];
    const uint32_t sb = smem_u32(smem);
    const uint32_t QH = 0, QL = 16384, STG = 32768;

    const int tid = threadIdx.x, wid = tid >> 5, lane = tid & 31;
    const int qt = (int)gridDim.x - 1 - (int)blockIdx.x;   // big tiles first
    const int h = blockIdx.y, b = blockIdx.z;
    const int q0 = qt * ABQ;
    const size_t rowbase = (size_t)b * SEQ;
    const int qcol = h * 64, kcol = 1024 + h * 64, vcol = 2048 + h * 64;

    // Q hi/lo tiles -> smem
    #pragma unroll
    for (int t = 0; t < 4; ++t) {
        int id = tid + t * 256;                  // 0..1023
        int r = id >> 3, c = id & 7;
        uint32_t so = SW128(r * 128 + c * 16);
        size_t grow = (rowbase + q0 + r) * TRIPLE + qcol + c * 8;
        cp16(sb + QH + so, qkh + grow);
        cp16(sb + QL + so, qkl + grow);
    }
    CP_COMMIT();

    const int T = (q0 + ABQ) / ABK;

    auto load_kv = [&](int t) {
        uint32_t st = sb + STG + (uint32_t)(t & 1) * 32768;
        int k0 = t * ABK;
        #pragma unroll
        for (int i = 0; i < 2; ++i) {
            int id = tid + i * 256;              // 0..511
            int r = id >> 3, c = id & 7;
            uint32_t so = SW128(r * 128 + c * 16);
            size_t grow = (rowbase + k0 + r) * TRIPLE;
            cp16(st + 0     + so, qkh + grow + kcol + c * 8);
            cp16(st + 8192  + so, qkl + grow + kcol + c * 8);
            cp16(st + 16384 + so, qkh + grow + vcol + c * 8);
            cp16(st + 24576 + so, qkl + grow + vcol + c * 8);
        }
        CP_COMMIT();
    };
    load_kv(0);
    CP_WAIT(0);
    __syncthreads();

    // Q fragments (persistent)
    uint32_t qhf[4][4], qlf[4][4];
    {
        int arow = wid * 16 + (lane & 15);
        int akb = (lane >> 4) * 16;
        #pragma unroll
        for (int ks = 0; ks < 4; ++ks) {
            ldmx4(qhf[ks], sb + QH + SW128((uint32_t)(arow * 128 + ks * 32 + akb)));
            ldmx4(qlf[ks], sb + QL + SW128((uint32_t)(arow * 128 + ks * 32 + akb)));
        }
    }

    float m_run[2] = { -1e30f, -1e30f }, l_run[2] = { 0.f, 0.f };
    float o_acc[8][4];
    #pragma unroll
    for (int nt = 0; nt < 8; ++nt)
        #pragma unroll
        for (int r = 0; r < 4; ++r) o_acc[nt][r] = 0.f;

    const int r0l = lane >> 2;
    const int qrow0 = q0 + wid * 16 + r0l;
    const int qrow1 = qrow0 + 8;
    const int ecol = (lane & 3) * 2;
    const int brow = lane & 7;
    const int bkb  = ((lane >> 3) & 1) * 16;
    const int vrow = lane & 15;

    for (int t = 0; t < T; ++t) {
        __syncthreads();                         // done reading stage (t+1)&1
        if (t + 1 < T) { load_kv(t + 1); CP_WAIT(1); } else { CP_WAIT(0); }
        __syncthreads();

        uint32_t st = sb + STG + (uint32_t)(t & 1) * 32768;

        // ---- S = Q K^T (split: qh*kh + ql*kh + qh*kl) ----
        float s_acc[8][4];
        #pragma unroll
        for (int nt = 0; nt < 8; ++nt)
            #pragma unroll
            for (int r = 0; r < 4; ++r) s_acc[nt][r] = 0.f;

        #pragma unroll
        for (int ks = 0; ks < 4; ++ks) {
            #pragma unroll
            for (int nt = 0; nt < 8; ++nt) {
                uint32_t khf[2], klf[2];
                uint32_t off = (uint32_t)((nt * 8 + brow) * 128 + ks * 32 + bkb);
                ldmx2(khf, st + 0 + SW128(off));
                ldmx2(klf, st + 8192 + SW128(off));
                mma16816(s_acc[nt], qhf[ks], khf);
                mma16816(s_acc[nt], qlf[ks], khf);
                mma16816(s_acc[nt], qhf[ks], klf);
            }
        }

        // ---- mask (before scale) + scale + online softmax ----
        const int kbase = t * ABK;
        float rmax0 = -3.0e38f, rmax1 = -3.0e38f;
        #pragma unroll
        for (int nt = 0; nt < 8; ++nt) {
            int kc = kbase + nt * 8 + ecol;
            float v0 = (kc     > qrow0) ? -1e9f : s_acc[nt][0];
            float v1 = (kc + 1 > qrow0) ? -1e9f : s_acc[nt][1];
            float v2 = (kc     > qrow1) ? -1e9f : s_acc[nt][2];
            float v3 = (kc + 1 > qrow1) ? -1e9f : s_acc[nt][3];
            v0 *= 0.125f; v1 *= 0.125f; v2 *= 0.125f; v3 *= 0.125f;
            s_acc[nt][0] = v0; s_acc[nt][1] = v1; s_acc[nt][2] = v2; s_acc[nt][3] = v3;
            rmax0 = fmaxf(rmax0, fmaxf(v0, v1));
            rmax1 = fmaxf(rmax1, fmaxf(v2, v3));
        }
        rmax0 = fmaxf(rmax0, __shfl_xor_sync(0xffffffffu, rmax0, 1));
        rmax0 = fmaxf(rmax0, __shfl_xor_sync(0xffffffffu, rmax0, 2));
        rmax1 = fmaxf(rmax1, __shfl_xor_sync(0xffffffffu, rmax1, 1));
        rmax1 = fmaxf(rmax1, __shfl_xor_sync(0xffffffffu, rmax1, 2));

        float mn0 = fmaxf(m_run[0], rmax0), mn1 = fmaxf(m_run[1], rmax1);
        float cr0 = __expf(m_run[0] - mn0), cr1 = __expf(m_run[1] - mn1);
        float ps0 = 0.f, ps1 = 0.f;

        uint32_t pha[4][4], pla[4][4];
        #pragma unroll
        for (int ks = 0; ks < 4; ++ks) {
            #pragma unroll
            for (int j = 0; j < 2; ++j) {
                int nt = 2 * ks + j;
                float p0 = __expf(s_acc[nt][0] - mn0);
                float p1 = __expf(s_acc[nt][1] - mn0);
                float p2 = __expf(s_acc[nt][2] - mn1);
                float p3 = __expf(s_acc[nt][3] - mn1);
                ps0 += p0 + p1; ps1 += p2 + p3;
                __nv_bfloat16 h0 = __float2bfloat16(p0), h1 = __float2bfloat16(p1);
                __nv_bfloat16 h2 = __float2bfloat16(p2), h3 = __float2bfloat16(p3);
                pha[ks][2 * j + 0] = packbf2(__bfloat162float(h0), __bfloat162float(h1));
                pha[ks][2 * j + 1] = packbf2(__bfloat162float(h2), __bfloat162float(h3));
                pla[ks][2 * j + 0] = packbf2(p0 - __bfloat162float(h0), p1 - __bfloat162float(h1));
                pla[ks][2 * j + 1] = packbf2(p2 - __bfloat162float(h2), p3 - __bfloat162float(h3));
            }
        }
        ps0 += __shfl_xor_sync(0xffffffffu, ps0, 1);
        ps0 += __shfl_xor_sync(0xffffffffu, ps0, 2);
        ps1 += __shfl_xor_sync(0xffffffffu, ps1, 1);
        ps1 += __shfl_xor_sync(0xffffffffu, ps1, 2);

        l_run[0] = l_run[0] * cr0 + ps0;
        l_run[1] = l_run[1] * cr1 + ps1;
        m_run[0] = mn0; m_run[1] = mn1;
        #pragma unroll
        for (int nt = 0; nt < 8; ++nt) {
            o_acc[nt][0] *= cr0; o_acc[nt][1] *= cr0;
            o_acc[nt][2] *= cr1; o_acc[nt][3] *= cr1;
        }

        // ---- O += P V (split: ph*vh + pl*vh + ph*vl) ----
        #pragma unroll
        for (int ks = 0; ks < 4; ++ks) {
            #pragma unroll
            for (int nt = 0; nt < 8; ++nt) {
                uint32_t vhf[2], vlf[2];
                uint32_t off = (uint32_t)((ks * 16 + vrow) * 128 + nt * 16);
                ldmx2t(vhf, st + 16384 + SW128(off));
                ldmx2t(vlf, st + 24576 + SW128(off));
                mma16816(o_acc[nt], pha[ks], vhf);
                mma16816(o_acc[nt], pla[ks], vhf);
                mma16816(o_acc[nt], pha[ks], vlf);
            }
        }
    }

    // ---- epilogue: normalize, write ctx as A' [hi|hi|lo] ----
    float inv0 = 1.0f / l_run[0], inv1 = 1.0f / l_run[1];
    size_t tok0 = rowbase + (size_t)q0 + wid * 16 + r0l;
    #pragma unroll
    for (int nt = 0; nt < 8; ++nt) {
        int gcol = h * 64 + nt * 8 + ecol;
        float v0 = o_acc[nt][0] * inv0, v1 = o_acc[nt][1] * inv0;
        float v2 = o_acc[nt][2] * inv1, v3 = o_acc[nt][3] * inv1;
        size_t b0 = tok0 * KP + gcol;
        size_t b1 = (tok0 + 8) * KP + gcol;
        // hi at k and k+1024, lo at k+2048
        __nv_bfloat16 h0 = __float2bfloat16(v0), h1 = __float2bfloat16(v1);
        __nv_bfloat16 h2 = __float2bfloat16(v2), h3 = __float2bfloat16(v3);
        __nv_bfloat162 hv0; hv0.x = h0; hv0.y = h1;
        __nv_bfloat162 hv1; hv1.x = h2; hv1.y = h3;
        __nv_bfloat162 lv0; lv0.x = __float2bfloat16(v0 - __bfloat162float(h0));
                            lv0.y = __float2bfloat16(v1 - __bfloat162float(h1));
        __nv_bfloat162 lv1; lv1.x = __float2bfloat16(v2 - __bfloat162float(h2));
                            lv1.y = __float2bfloat16(v3 - __bfloat162float(h3));
        *reinterpret_cast<__nv_bfloat162*>(&ctxA[b0])        = hv0;
        *reinterpret_cast<__nv_bfloat162*>(&ctxA[b0 + 1024]) = hv0;
        *reinterpret_cast<__nv_bfloat162*>(&ctxA[b0 + 2048]) = lv0;
        *reinterpret_cast<__nv_bfloat162*>(&ctxA[b1])        = hv1;
        *reinterpret_cast<__nv_bfloat162*>(&ctxA[b1 + 1024]) = hv1;
        *reinterpret_cast<__nv_bfloat162*>(&ctxA[b1 + 2048]) = lv1;
    }
}

// ============================ launch =========================================
extern "C" void kernel_launch(void* const* d_in, const int* in_sizes, int n_in,
                              void* d_out, int out_size)
{
    (void)in_sizes; (void)n_in; (void)out_size;
    const float* x      = (const float*)d_in[0];
    const float* W_qkv  = (const float*)d_in[1];
    const float* b_qkv  = (const float*)d_in[2];
    const float* W_proj = (const float*)d_in[3];
    const float* b_proj = (const float*)d_in[4];
    float* out = (float*)d_out;

    __nv_bfloat16 *a_buf, *wq_buf, *wp_buf, *qh_buf, *ql_buf;
    cudaGetSymbolAddress((void**)&a_buf, g_a);
    cudaGetSymbolAddress((void**)&wq_buf, g_wq);
    cudaGetSymbolAddress((void**)&wp_buf, g_wp);
    cudaGetSymbolAddress((void**)&qh_buf, g_qh);
    cudaGetSymbolAddress((void**)&ql_buf, g_ql);

    static bool attr_set = false;
    if (!attr_set) {
        cudaFuncSetAttribute(gemm_hmma_kernel<0>, cudaFuncAttributeMaxDynamicSharedMemorySize, GEMM_SMEM);
        cudaFuncSetAttribute(gemm_hmma_kernel<1>, cudaFuncAttributeMaxDynamicSharedMemorySize, GEMM_SMEM);
        cudaFuncSetAttribute(attn_hmma_kernel, cudaFuncAttributeMaxDynamicSharedMemorySize, ATTN_SMEM);
        attr_set = true;
    }

    // 1) convert x and weights to bf16 splits
    convert_a_kernel<<<(NTOK * D_MODEL + 255) / 256, 256>>>(x, a_buf, NTOK * D_MODEL);
    {
        dim3 grid(TRIPLE / 32, D_MODEL / 32);
        convert_w_kernel<<<grid, dim3(32, 8)>>>(W_qkv, wq_buf, TRIPLE);
    }
    {
        dim3 grid(D_MODEL / 32, D_MODEL / 32);
        convert_w_kernel<<<grid, dim3(32, 8)>>>(W_proj, wp_buf, D_MODEL);
    }

    // 2) QKV GEMM -> bf16 hi/lo qkv
    {
        dim3 grid(TRIPLE / 128, NTOK / 128);
        gemm_hmma_kernel<1><<<grid, 256, GEMM_SMEM>>>(a_buf, wq_buf, b_qkv, nullptr, qh_buf, ql_buf, TRIPLE);
    }

    // 3) HMMA flash attention -> ctx in A' layout (overwrites g_a)
    {
        dim3 grid(SEQ / ABQ, N_HEADS, BATCH);
        attn_hmma_kernel<<<grid, 256, ATTN_SMEM>>>(qh_buf, ql_buf, a_buf);
    }

    // 4) output projection (fp32 out + bias)
    {
        dim3 grid(D_MODEL / 128, NTOK / 128);
        gemm_hmma_kernel<0><<<grid, 256, GEMM_SMEM>>>(a_buf, wp_buf, b_proj, out, nullptr, nullptr, D_MODEL);
    }
}